// round 2
// baseline (speedup 1.0000x reference)
#include <cuda_runtime.h>
#include <cuda_bf16.h>
#include <cstdint>

// GCN layer: out = ReLU( segment_sum(feature[src], dst) @ W^T + b )
// N=100000 nodes, E=1.6M edges, 128 in/out feats, fp32.
// NOTE: src/dst arrive as int32 (JAX x64 disabled downcasts jnp.int64).
//
//   k1: zero g_agg (device-global scratch, 51.2 MB)
//   k2: edge scatter: warp per edge, float4 gather of feature[src],
//       red.global.add.v4.f32 into g_agg[dst]   (vector RED, no return)
//   k3: GEMM 100000x128x128 with W^T in smem (transposed, pad 132),
//       8x4 register blocking, fused bias + ReLU epilogue.

#define N_FEATS 128

__device__ float g_agg[100000 * N_FEATS];

// ---------------------------------------------------------------------------
// k1: zero the aggregation buffer (float4 grid-stride)
// ---------------------------------------------------------------------------
__global__ void __launch_bounds__(256) zero_agg_kernel(int n_float4) {
    float4 z = make_float4(0.f, 0.f, 0.f, 0.f);
    float4* p = reinterpret_cast<float4*>(g_agg);
    for (int i = blockIdx.x * blockDim.x + threadIdx.x; i < n_float4;
         i += gridDim.x * blockDim.x) {
        p[i] = z;
    }
}

// ---------------------------------------------------------------------------
// k2: scatter-aggregate. One warp per edge per iteration.
// Each lane handles 4 contiguous floats (float4 gather + vector RED).
// ---------------------------------------------------------------------------
__global__ void __launch_bounds__(256) scatter_kernel(
    const float* __restrict__ feat,
    const int* __restrict__ src,
    const int* __restrict__ dst,
    int n_edges)
{
    const int lane    = threadIdx.x & 31;
    const int warp    = (blockIdx.x * blockDim.x + threadIdx.x) >> 5;
    const int n_warps = (gridDim.x * blockDim.x) >> 5;

    for (int e = warp; e < n_edges; e += n_warps) {
        const int s = __ldg(&src[e]);
        const int d = __ldg(&dst[e]);
        const float4 v = *reinterpret_cast<const float4*>(
            feat + (size_t)s * N_FEATS + lane * 4);
        float* p = g_agg + (size_t)d * N_FEATS + lane * 4;
        asm volatile(
            "red.global.add.v4.f32 [%0], {%1, %2, %3, %4};"
            :: "l"(p), "f"(v.x), "f"(v.y), "f"(v.z), "f"(v.w)
            : "memory");
    }
}

// ---------------------------------------------------------------------------
// k3: out = ReLU(agg @ W^T + b)
// Block: 256 threads, tile = 64 rows x 128 cols.
// Thread (tx=tid%32, ty=tid/32): rows ty*8..ty*8+7, cols tx*4..tx*4+3.
// W stored transposed in dynamic smem as Wt[k][c], row stride 132 floats.
// ---------------------------------------------------------------------------
#define WT_STRIDE 132

__global__ void __launch_bounds__(256) gemm_bias_relu_kernel(
    const float* __restrict__ W,   // [128, 128] row-major: W[c][k]
    const float* __restrict__ bias,
    float* __restrict__ out,
    int M)
{
    extern __shared__ float Wt[];  // [128][WT_STRIDE]

    const int tid = threadIdx.x;
    const int tx  = tid & 31;   // column group
    const int ty  = tid >> 5;   // row group

    // Load W transposed into smem: Wt[k*WT_STRIDE + c] = W[c*128 + k]
    #pragma unroll
    for (int i = tid; i < 128 * 128; i += 256) {
        int c = i >> 7;
        int k = i & 127;
        Wt[k * WT_STRIDE + c] = W[i];
    }
    __syncthreads();

    const int row0 = blockIdx.x * 64 + ty * 8;

    // Clamped row pointers (safe loads for the ragged last block)
    const float* ap[8];
    #pragma unroll
    for (int r = 0; r < 8; r++) {
        int rr = row0 + r;
        if (rr > M - 1) rr = M - 1;
        ap[r] = g_agg + (size_t)rr * N_FEATS;
    }

    float acc[8][4];
    #pragma unroll
    for (int r = 0; r < 8; r++)
        #pragma unroll
        for (int j = 0; j < 4; j++)
            acc[r][j] = 0.f;

    #pragma unroll 4
    for (int k = 0; k < 128; k++) {
        const float4 w = *reinterpret_cast<const float4*>(
            &Wt[k * WT_STRIDE + tx * 4]);
        #pragma unroll
        for (int r = 0; r < 8; r++) {
            const float f = __ldg(&ap[r][k]);
            acc[r][0] = fmaf(f, w.x, acc[r][0]);
            acc[r][1] = fmaf(f, w.y, acc[r][1]);
            acc[r][2] = fmaf(f, w.z, acc[r][2]);
            acc[r][3] = fmaf(f, w.w, acc[r][3]);
        }
    }

    const float4 bv = *reinterpret_cast<const float4*>(bias + tx * 4);

    #pragma unroll
    for (int r = 0; r < 8; r++) {
        const int row = row0 + r;
        if (row < M) {
            float4 o;
            o.x = fmaxf(acc[r][0] + bv.x, 0.f);
            o.y = fmaxf(acc[r][1] + bv.y, 0.f);
            o.z = fmaxf(acc[r][2] + bv.z, 0.f);
            o.w = fmaxf(acc[r][3] + bv.w, 0.f);
            *reinterpret_cast<float4*>(out + (size_t)row * N_FEATS + tx * 4) = o;
        }
    }
}

// ---------------------------------------------------------------------------
extern "C" void kernel_launch(void* const* d_in, const int* in_sizes, int n_in,
                              void* d_out, int out_size)
{
    const float* feat = (const float*)d_in[0];
    const int*   src  = (const int*)d_in[1];
    const int*   dst  = (const int*)d_in[2];
    const float* W    = (const float*)d_in[3];
    const float* bias = (const float*)d_in[4];
    float*       out  = (float*)d_out;

    const int n_edges = in_sizes[1];
    const int M       = in_sizes[0] / N_FEATS;  // 100000 nodes

    const int smem_bytes = 128 * WT_STRIDE * (int)sizeof(float);  // 67584
    cudaFuncSetAttribute(gemm_bias_relu_kernel,
                         cudaFuncAttributeMaxDynamicSharedMemorySize,
                         smem_bytes);

    // k1: zero agg
    {
        int n_f4 = (M * N_FEATS) / 4;
        zero_agg_kernel<<<1184, 256>>>(n_f4);
    }
    // k2: scatter-aggregate
    scatter_kernel<<<1184, 256>>>(feat, src, dst, n_edges);

    // k3: GEMM + bias + ReLU
    {
        int grid = (M + 63) / 64;
        gemm_bias_relu_kernel<<<grid, 256, smem_bytes>>>(W, bias, out, M);
    }
}

// round 3
// speedup vs baseline: 1.1829x; 1.1829x over previous
#include <cuda_runtime.h>
#include <cuda_bf16.h>
#include <cstdint>

// GCN layer: out = ReLU( segment_sum(feature[src], dst) @ W^T + b )
// N=100000 nodes, E=1.6M edges, 128 feats, fp32. src/dst are int32.
//
// R3 strategy: eliminate the L2 atomic-ALU bottleneck by building CSR
// (sorted-by-dst edge list) on device, then atomic-free warp-per-node
// gather-aggregate; GEMM upgraded to packed fma.rn.f32x2 (2x fp32 rate).

#define N_FEATS   128
#define MAX_NODES 100000
#define MAX_EDGES 1600000
#define SCAN_BLK  1024
#define N_SCAN_BLKS ((MAX_NODES + SCAN_BLK - 1) / SCAN_BLK)   // 98

__device__ float g_agg[MAX_NODES * N_FEATS];
__device__ int   g_deg[MAX_NODES];
__device__ int   g_off[MAX_NODES + 1];
__device__ int   g_pos[MAX_NODES];
__device__ int   g_bsum[N_SCAN_BLKS];
__device__ int   g_boff[N_SCAN_BLKS];
__device__ int   g_edge_src[MAX_EDGES];

// ---------------------------------------------------------------------------
// zero degree counters
// ---------------------------------------------------------------------------
__global__ void __launch_bounds__(256) zero_deg_kernel(int n) {
    for (int i = blockIdx.x * blockDim.x + threadIdx.x; i < n;
         i += gridDim.x * blockDim.x)
        g_deg[i] = 0;
}

// ---------------------------------------------------------------------------
// degree histogram
// ---------------------------------------------------------------------------
__global__ void __launch_bounds__(256) hist_kernel(
    const int* __restrict__ dst, int n_edges)
{
    for (int e = blockIdx.x * blockDim.x + threadIdx.x; e < n_edges;
         e += gridDim.x * blockDim.x)
        atomicAdd(&g_deg[dst[e]], 1);
}

// ---------------------------------------------------------------------------
// scan phase 1: per-block exclusive scan of g_deg -> g_off, block sums -> g_bsum
// ---------------------------------------------------------------------------
__global__ void __launch_bounds__(SCAN_BLK) scan1_kernel(int n) {
    __shared__ int warp_sums[32];
    const int t = threadIdx.x;
    const int i = blockIdx.x * SCAN_BLK + t;
    const int lane = t & 31;
    const int wid  = t >> 5;

    int v = (i < n) ? g_deg[i] : 0;

    // inclusive warp scan
    int incl = v;
    #pragma unroll
    for (int d = 1; d < 32; d <<= 1) {
        int y = __shfl_up_sync(0xffffffffu, incl, d);
        if (lane >= d) incl += y;
    }
    if (lane == 31) warp_sums[wid] = incl;
    __syncthreads();

    if (wid == 0) {
        int s = warp_sums[lane];
        #pragma unroll
        for (int d = 1; d < 32; d <<= 1) {
            int y = __shfl_up_sync(0xffffffffu, s, d);
            if (lane >= d) s += y;
        }
        warp_sums[lane] = s;
    }
    __syncthreads();

    int woff = (wid > 0) ? warp_sums[wid - 1] : 0;
    int excl = woff + incl - v;

    if (i < n) g_off[i] = excl;
    if (t == SCAN_BLK - 1) g_bsum[blockIdx.x] = woff + incl;
}

// ---------------------------------------------------------------------------
// scan phase 2: serial scan of the 98 block sums (tiny)
// ---------------------------------------------------------------------------
__global__ void scan2_kernel(int nblk) {
    int run = 0;
    for (int b = 0; b < nblk; b++) {
        g_boff[b] = run;
        run += g_bsum[b];
    }
}

// ---------------------------------------------------------------------------
// scan phase 3: add block offsets; init g_pos; write sentinel
// ---------------------------------------------------------------------------
__global__ void __launch_bounds__(256) scan3_kernel(int n, int n_edges) {
    int i = blockIdx.x * blockDim.x + threadIdx.x;
    if (i < n) {
        int off = g_off[i] + g_boff[i >> 10];
        g_off[i] = off;
        g_pos[i] = off;
    }
    if (i == 0) g_off[n] = n_edges;
}

// ---------------------------------------------------------------------------
// fill: bucket edge src ids by dst (atomic cursor claim)
// ---------------------------------------------------------------------------
__global__ void __launch_bounds__(256) fill_kernel(
    const int* __restrict__ src, const int* __restrict__ dst, int n_edges)
{
    for (int e = blockIdx.x * blockDim.x + threadIdx.x; e < n_edges;
         e += gridDim.x * blockDim.x) {
        int p = atomicAdd(&g_pos[dst[e]], 1);
        g_edge_src[p] = src[e];
    }
}

// ---------------------------------------------------------------------------
// gather-aggregate: warp per node, atomic-free. Lane owns 4 contiguous feats.
// Edge ids are loaded coalesced (32 at a time) and broadcast via shuffle.
// ---------------------------------------------------------------------------
__global__ void __launch_bounds__(256) gather_kernel(
    const float* __restrict__ feat, int n_nodes)
{
    const int lane    = threadIdx.x & 31;
    const int warp    = (blockIdx.x * blockDim.x + threadIdx.x) >> 5;
    const int n_warps = (gridDim.x * blockDim.x) >> 5;

    for (int n = warp; n < n_nodes; n += n_warps) {
        const int beg = g_off[n];
        const int end = g_off[n + 1];

        float4 acc = make_float4(0.f, 0.f, 0.f, 0.f);

        for (int i = beg; i < end; i += 32) {
            const int cnt = min(32, end - i);
            int s = (lane < cnt) ? g_edge_src[i + lane] : 0;
            #pragma unroll 4
            for (int j = 0; j < cnt; j++) {
                const int sj = __shfl_sync(0xffffffffu, s, j);
                const float4 v = *reinterpret_cast<const float4*>(
                    feat + (size_t)sj * N_FEATS + lane * 4);
                acc.x += v.x; acc.y += v.y; acc.z += v.z; acc.w += v.w;
            }
        }
        *reinterpret_cast<float4*>(g_agg + (size_t)n * N_FEATS + lane * 4) = acc;
    }
}

// ---------------------------------------------------------------------------
// GEMM + bias + ReLU, packed f32x2 FFMA (2x fp32 rate vs scalar FFMA).
// Block: 256 thr; tile 64 rows x 128 cols; thread: 8 rows x 4 cols.
// ---------------------------------------------------------------------------
#define WT_STRIDE 132

__device__ __forceinline__ unsigned long long pk2(float f) {
    unsigned long long r;
    asm("mov.b64 %0, {%1, %1};" : "=l"(r) : "f"(f));
    return r;
}
#define FMA2(d, a, b) \
    asm("fma.rn.f32x2 %0, %1, %2, %0;" : "+l"(d) : "l"(a), "l"(b))

__global__ void __launch_bounds__(256) gemm_bias_relu_kernel(
    const float* __restrict__ W,   // [128,128] row-major: W[c][k]
    const float* __restrict__ bias,
    float* __restrict__ out,
    int M)
{
    extern __shared__ float Wt[];  // [128][WT_STRIDE], Wt[k][c] = W[c][k]

    const int tid = threadIdx.x;
    const int tx  = tid & 31;   // column group (4 cols)
    const int ty  = tid >> 5;   // row group (8 rows)

    #pragma unroll
    for (int i = tid; i < 128 * 128; i += 256) {
        int c = i >> 7;
        int k = i & 127;
        Wt[k * WT_STRIDE + c] = W[i];
    }
    __syncthreads();

    const int row0 = blockIdx.x * 64 + ty * 8;

    const float* ap[8];
    #pragma unroll
    for (int r = 0; r < 8; r++) {
        int rr = row0 + r;
        if (rr > M - 1) rr = M - 1;
        ap[r] = g_agg + (size_t)rr * N_FEATS;
    }

    unsigned long long acc[8][2];
    #pragma unroll
    for (int r = 0; r < 8; r++) { acc[r][0] = 0ull; acc[r][1] = 0ull; }

    #pragma unroll 2
    for (int k0 = 0; k0 < 128; k0 += 4) {
        ulonglong2 wv[4];
        #pragma unroll
        for (int kk = 0; kk < 4; kk++)
            wv[kk] = *reinterpret_cast<const ulonglong2*>(
                &Wt[(k0 + kk) * WT_STRIDE + tx * 4]);

        #pragma unroll
        for (int r = 0; r < 8; r++) {
            const float4 a4 = *reinterpret_cast<const float4*>(ap[r] + k0);
            const unsigned long long f0 = pk2(a4.x);
            const unsigned long long f1 = pk2(a4.y);
            const unsigned long long f2 = pk2(a4.z);
            const unsigned long long f3 = pk2(a4.w);
            FMA2(acc[r][0], f0, wv[0].x);  FMA2(acc[r][1], f0, wv[0].y);
            FMA2(acc[r][0], f1, wv[1].x);  FMA2(acc[r][1], f1, wv[1].y);
            FMA2(acc[r][0], f2, wv[2].x);  FMA2(acc[r][1], f2, wv[2].y);
            FMA2(acc[r][0], f3, wv[3].x);  FMA2(acc[r][1], f3, wv[3].y);
        }
    }

    const float4 bv = *reinterpret_cast<const float4*>(bias + tx * 4);

    #pragma unroll
    for (int r = 0; r < 8; r++) {
        const int row = row0 + r;
        if (row < M) {
            float a0, a1, a2, a3;
            asm("mov.b64 {%0, %1}, %2;" : "=f"(a0), "=f"(a1) : "l"(acc[r][0]));
            asm("mov.b64 {%0, %1}, %2;" : "=f"(a2), "=f"(a3) : "l"(acc[r][1]));
            float4 o;
            o.x = fmaxf(a0 + bv.x, 0.f);
            o.y = fmaxf(a1 + bv.y, 0.f);
            o.z = fmaxf(a2 + bv.z, 0.f);
            o.w = fmaxf(a3 + bv.w, 0.f);
            *reinterpret_cast<float4*>(out + (size_t)row * N_FEATS + tx * 4) = o;
        }
    }
}

// ---------------------------------------------------------------------------
extern "C" void kernel_launch(void* const* d_in, const int* in_sizes, int n_in,
                              void* d_out, int out_size)
{
    const float* feat = (const float*)d_in[0];
    const int*   src  = (const int*)d_in[1];
    const int*   dst  = (const int*)d_in[2];
    const float* W    = (const float*)d_in[3];
    const float* bias = (const float*)d_in[4];
    float*       out  = (float*)d_out;

    const int n_edges = in_sizes[1];
    const int M       = in_sizes[0] / N_FEATS;   // 100000 nodes
    const int nblk    = (M + SCAN_BLK - 1) / SCAN_BLK;

    const int smem_bytes = 128 * WT_STRIDE * (int)sizeof(float);  // 67584
    cudaFuncSetAttribute(gemm_bias_relu_kernel,
                         cudaFuncAttributeMaxDynamicSharedMemorySize,
                         smem_bytes);

    // CSR build
    zero_deg_kernel<<<(M + 255) / 256, 256>>>(M);
    hist_kernel<<<1184, 256>>>(dst, n_edges);
    scan1_kernel<<<nblk, SCAN_BLK>>>(M);
    scan2_kernel<<<1, 1>>>(nblk);
    scan3_kernel<<<(M + 255) / 256, 256>>>(M, n_edges);
    fill_kernel<<<1184, 256>>>(src, dst, n_edges);

    // atomic-free aggregate
    gather_kernel<<<1184, 256>>>(feat, M);

    // GEMM + bias + ReLU
    gemm_bias_relu_kernel<<<(M + 63) / 64, 256, smem_bytes>>>(W, bias, out, M);
}

// round 4
// speedup vs baseline: 1.2941x; 1.0940x over previous
#include <cuda_runtime.h>
#include <cuda_bf16.h>
#include <cstdint>

// GCN layer: out = ReLU( segment_sum(feature[src], dst) @ W^T + b )
// N=100000, E=1.6M, 128 feats, fp32. src/dst int32.
//
// R4: linear commutes with segment_sum ->
//       Y = feat @ W^T   (independent of edges; forked to stream s2)
//       CSR build (memset/hist/scan/fill) on main stream, CONCURRENT with GEMM
//       join, then atomic-free gather over Y + bias + ReLU -> out
// scan2 upgraded from 1 thread to a 128-thread shuffle scan.

#define N_FEATS   128
#define MAX_NODES 100000
#define MAX_EDGES 1600000
#define SCAN_BLK  1024
#define N_SCAN_BLKS ((MAX_NODES + SCAN_BLK - 1) / SCAN_BLK)   // 98

__device__ float g_y[MAX_NODES * N_FEATS];     // Y = feat @ W^T
__device__ int   g_deg[MAX_NODES];
__device__ int   g_off[MAX_NODES + 1];
__device__ int   g_pos[MAX_NODES];
__device__ int   g_bsum[N_SCAN_BLKS];
__device__ int   g_boff[N_SCAN_BLKS];
__device__ int   g_edge_src[MAX_EDGES];

// ---------------------------------------------------------------------------
// degree histogram
// ---------------------------------------------------------------------------
__global__ void __launch_bounds__(256) hist_kernel(
    const int* __restrict__ dst, int n_edges)
{
    for (int e = blockIdx.x * blockDim.x + threadIdx.x; e < n_edges;
         e += gridDim.x * blockDim.x)
        atomicAdd(&g_deg[dst[e]], 1);
}

// ---------------------------------------------------------------------------
// scan phase 1: per-block exclusive scan of g_deg -> g_off, block sums
// ---------------------------------------------------------------------------
__global__ void __launch_bounds__(SCAN_BLK) scan1_kernel(int n) {
    __shared__ int warp_sums[32];
    const int t = threadIdx.x;
    const int i = blockIdx.x * SCAN_BLK + t;
    const int lane = t & 31;
    const int wid  = t >> 5;

    int v = (i < n) ? g_deg[i] : 0;

    int incl = v;
    #pragma unroll
    for (int d = 1; d < 32; d <<= 1) {
        int y = __shfl_up_sync(0xffffffffu, incl, d);
        if (lane >= d) incl += y;
    }
    if (lane == 31) warp_sums[wid] = incl;
    __syncthreads();

    if (wid == 0) {
        int s = warp_sums[lane];
        #pragma unroll
        for (int d = 1; d < 32; d <<= 1) {
            int y = __shfl_up_sync(0xffffffffu, s, d);
            if (lane >= d) s += y;
        }
        warp_sums[lane] = s;
    }
    __syncthreads();

    int woff = (wid > 0) ? warp_sums[wid - 1] : 0;
    int excl = woff + incl - v;

    if (i < n) g_off[i] = excl;
    if (t == SCAN_BLK - 1) g_bsum[blockIdx.x] = woff + incl;
}

// ---------------------------------------------------------------------------
// scan phase 2: block-parallel scan of the 98 block sums (one 128-thr block)
// ---------------------------------------------------------------------------
__global__ void __launch_bounds__(128) scan2_kernel(int nblk) {
    __shared__ int ws[4];
    const int t = threadIdx.x;
    const int lane = t & 31;
    const int wid  = t >> 5;

    int v = (t < nblk) ? g_bsum[t] : 0;

    int incl = v;
    #pragma unroll
    for (int d = 1; d < 32; d <<= 1) {
        int y = __shfl_up_sync(0xffffffffu, incl, d);
        if (lane >= d) incl += y;
    }
    if (lane == 31) ws[wid] = incl;
    __syncthreads();

    int pre = 0;
    #pragma unroll
    for (int w = 0; w < 4; w++)
        if (w < wid) pre += ws[w];

    if (t < nblk) g_boff[t] = pre + incl - v;   // exclusive
}

// ---------------------------------------------------------------------------
// scan phase 3: add block offsets; init g_pos; write sentinel
// ---------------------------------------------------------------------------
__global__ void __launch_bounds__(256) scan3_kernel(int n, int n_edges) {
    int i = blockIdx.x * blockDim.x + threadIdx.x;
    if (i < n) {
        int off = g_off[i] + g_boff[i >> 10];
        g_off[i] = off;
        g_pos[i] = off;
    }
    if (i == 0) g_off[n] = n_edges;
}

// ---------------------------------------------------------------------------
// fill: bucket edge src ids by dst (atomic cursor claim)
// ---------------------------------------------------------------------------
__global__ void __launch_bounds__(256) fill_kernel(
    const int* __restrict__ src, const int* __restrict__ dst, int n_edges)
{
    for (int e = blockIdx.x * blockDim.x + threadIdx.x; e < n_edges;
         e += gridDim.x * blockDim.x) {
        int p = atomicAdd(&g_pos[dst[e]], 1);
        g_edge_src[p] = src[e];
    }
}

// ---------------------------------------------------------------------------
// GEMM: Y = feat @ W^T   (no bias/relu here — those apply post-aggregation)
// Packed fma.rn.f32x2 (2x fp32 rate). Tile 64 rows x 128 cols per block.
// ---------------------------------------------------------------------------
#define WT_STRIDE 132

__device__ __forceinline__ unsigned long long pk2(float f) {
    unsigned long long r;
    asm("mov.b64 %0, {%1, %1};" : "=l"(r) : "f"(f));
    return r;
}
#define FMA2(d, a, b) \
    asm("fma.rn.f32x2 %0, %1, %2, %0;" : "+l"(d) : "l"(a), "l"(b))

__global__ void __launch_bounds__(256) gemm_kernel(
    const float* __restrict__ feat,   // [M, 128]
    const float* __restrict__ W,      // [128, 128] row-major: W[c][k]
    int M)
{
    extern __shared__ float Wt[];  // [128][WT_STRIDE], Wt[k][c] = W[c][k]

    const int tid = threadIdx.x;
    const int tx  = tid & 31;   // column group (4 cols)
    const int ty  = tid >> 5;   // row group (8 rows)

    #pragma unroll
    for (int i = tid; i < 128 * 128; i += 256) {
        int c = i >> 7;
        int k = i & 127;
        Wt[k * WT_STRIDE + c] = W[i];
    }
    __syncthreads();

    const int row0 = blockIdx.x * 64 + ty * 8;

    const float* ap[8];
    #pragma unroll
    for (int r = 0; r < 8; r++) {
        int rr = row0 + r;
        if (rr > M - 1) rr = M - 1;
        ap[r] = feat + (size_t)rr * N_FEATS;
    }

    unsigned long long acc[8][2];
    #pragma unroll
    for (int r = 0; r < 8; r++) { acc[r][0] = 0ull; acc[r][1] = 0ull; }

    #pragma unroll 2
    for (int k0 = 0; k0 < 128; k0 += 4) {
        ulonglong2 wv[4];
        #pragma unroll
        for (int kk = 0; kk < 4; kk++)
            wv[kk] = *reinterpret_cast<const ulonglong2*>(
                &Wt[(k0 + kk) * WT_STRIDE + tx * 4]);

        #pragma unroll
        for (int r = 0; r < 8; r++) {
            const float4 a4 = *reinterpret_cast<const float4*>(ap[r] + k0);
            const unsigned long long f0 = pk2(a4.x);
            const unsigned long long f1 = pk2(a4.y);
            const unsigned long long f2 = pk2(a4.z);
            const unsigned long long f3 = pk2(a4.w);
            FMA2(acc[r][0], f0, wv[0].x);  FMA2(acc[r][1], f0, wv[0].y);
            FMA2(acc[r][0], f1, wv[1].x);  FMA2(acc[r][1], f1, wv[1].y);
            FMA2(acc[r][0], f2, wv[2].x);  FMA2(acc[r][1], f2, wv[2].y);
            FMA2(acc[r][0], f3, wv[3].x);  FMA2(acc[r][1], f3, wv[3].y);
        }
    }

    #pragma unroll
    for (int r = 0; r < 8; r++) {
        const int row = row0 + r;
        if (row < M) {
            float a0, a1, a2, a3;
            asm("mov.b64 {%0, %1}, %2;" : "=f"(a0), "=f"(a1) : "l"(acc[r][0]));
            asm("mov.b64 {%0, %1}, %2;" : "=f"(a2), "=f"(a3) : "l"(acc[r][1]));
            float4 o = make_float4(a0, a1, a2, a3);
            *reinterpret_cast<float4*>(g_y + (size_t)row * N_FEATS + tx * 4) = o;
        }
    }
}

// ---------------------------------------------------------------------------
// gather-aggregate over Y, fused bias + ReLU epilogue -> out.
// Warp per node, atomic-free; lane owns 4 contiguous feats.
// ---------------------------------------------------------------------------
__global__ void __launch_bounds__(256) gather_epi_kernel(
    const float* __restrict__ bias,
    float* __restrict__ out,
    int n_nodes)
{
    const int lane    = threadIdx.x & 31;
    const int warp    = (blockIdx.x * blockDim.x + threadIdx.x) >> 5;
    const int n_warps = (gridDim.x * blockDim.x) >> 5;

    const float4 bv = *reinterpret_cast<const float4*>(bias + lane * 4);

    for (int n = warp; n < n_nodes; n += n_warps) {
        const int beg = g_off[n];
        const int end = g_off[n + 1];

        float4 acc = make_float4(0.f, 0.f, 0.f, 0.f);

        for (int i = beg; i < end; i += 32) {
            const int cnt = min(32, end - i);
            int s = (lane < cnt) ? g_edge_src[i + lane] : 0;
            #pragma unroll 4
            for (int j = 0; j < cnt; j++) {
                const int sj = __shfl_sync(0xffffffffu, s, j);
                const float4 v = *reinterpret_cast<const float4*>(
                    g_y + (size_t)sj * N_FEATS + lane * 4);
                acc.x += v.x; acc.y += v.y; acc.z += v.z; acc.w += v.w;
            }
        }

        float4 o;
        o.x = fmaxf(acc.x + bv.x, 0.f);
        o.y = fmaxf(acc.y + bv.y, 0.f);
        o.z = fmaxf(acc.z + bv.z, 0.f);
        o.w = fmaxf(acc.w + bv.w, 0.f);
        *reinterpret_cast<float4*>(out + (size_t)n * N_FEATS + lane * 4) = o;
    }
}

// ---------------------------------------------------------------------------
extern "C" void kernel_launch(void* const* d_in, const int* in_sizes, int n_in,
                              void* d_out, int out_size)
{
    const float* feat = (const float*)d_in[0];
    const int*   src  = (const int*)d_in[1];
    const int*   dst  = (const int*)d_in[2];
    const float* W    = (const float*)d_in[3];
    const float* bias = (const float*)d_in[4];
    float*       out  = (float*)d_out;

    const int n_edges = in_sizes[1];
    const int M       = in_sizes[0] / N_FEATS;   // 100000 nodes
    const int nblk    = (M + SCAN_BLK - 1) / SCAN_BLK;

    const int smem_bytes = 128 * WT_STRIDE * (int)sizeof(float);  // 67584
    cudaFuncSetAttribute(gemm_kernel,
                         cudaFuncAttributeMaxDynamicSharedMemorySize,
                         smem_bytes);

    // Fork: GEMM runs on s2 concurrently with the CSR build on the main
    // stream. Event fork/join keeps this graph-capturable (parallel branches).
    // Streams/events are created and destroyed per call: at graph-replay time
    // the host code doesn't run, so this costs nothing where it matters.
    cudaStream_t s2;
    cudaStreamCreateWithFlags(&s2, cudaStreamNonBlocking);
    cudaEvent_t ev_fork, ev_join;
    cudaEventCreateWithFlags(&ev_fork, cudaEventDisableTiming);
    cudaEventCreateWithFlags(&ev_join, cudaEventDisableTiming);

    // main stream: zero degree counters (must precede hist)
    void* deg_ptr = nullptr;
    cudaGetSymbolAddress(&deg_ptr, g_deg);
    cudaMemsetAsync(deg_ptr, 0, (size_t)M * sizeof(int), 0);

    // fork the GEMM branch
    cudaEventRecord(ev_fork, 0);
    cudaStreamWaitEvent(s2, ev_fork, 0);
    gemm_kernel<<<(M + 63) / 64, 256, smem_bytes, s2>>>(feat, W, M);
    cudaEventRecord(ev_join, s2);

    // main stream: CSR build
    hist_kernel<<<1184, 256>>>(dst, n_edges);
    scan1_kernel<<<nblk, SCAN_BLK>>>(M);
    scan2_kernel<<<1, 128>>>(nblk);
    scan3_kernel<<<(M + 255) / 256, 256>>>(M, n_edges);
    fill_kernel<<<1184, 256>>>(src, dst, n_edges);

    // join GEMM branch, then gather + bias + ReLU
    cudaStreamWaitEvent(0, ev_join, 0);
    gather_epi_kernel<<<1184, 256>>>(bias, out, M);

    cudaEventDestroy(ev_fork);
    cudaEventDestroy(ev_join);
    cudaStreamDestroy(s2);
}

// round 5
// speedup vs baseline: 1.3657x; 1.0553x over previous
#include <cuda_runtime.h>
#include <cuda_bf16.h>
#include <cstdint>

// GCN layer: out = ReLU( segment_sum(feature[src], dst) @ W^T + b )
// N=100000, E=1.6M, 128 feats, fp32. src/dst int32.
//
// R5: column-split software pipeline.
//   s2 :  GEMM_A (Y cols 0..63) -> GEMM_B (Y cols 64..127)
//   main: memset -> hist(+rank) -> scan1 -> scan3(lookback) -> fill
//         -> [wait GEMM_A] gather_A -> [wait GEMM_B] gather_B
// fill is atomic-free (rank captured during hist). scan2 eliminated.

#define N_FEATS   128
#define MAX_NODES 100000
#define MAX_EDGES 1600000
#define SCAN_BLK  1024
#define N_SCAN_BLKS ((MAX_NODES + SCAN_BLK - 1) / SCAN_BLK)   // 98

__device__ float g_y[MAX_NODES * N_FEATS];     // Y = feat @ W^T
__device__ int   g_deg[MAX_NODES];
__device__ int   g_off[MAX_NODES + 1];
__device__ int   g_bsum[N_SCAN_BLKS];
__device__ int   g_rank[MAX_EDGES];
__device__ int   g_edge_src[MAX_EDGES];

// ---------------------------------------------------------------------------
// hist + rank capture: g_rank[e] = position of edge e within its dst bucket
// ---------------------------------------------------------------------------
__global__ void __launch_bounds__(256) hist_rank_kernel(
    const int* __restrict__ dst, int n_edges)
{
    const int tid    = blockIdx.x * blockDim.x + threadIdx.x;
    const int stride = gridDim.x * blockDim.x;
    const int n4     = n_edges >> 2;

    for (int e4 = tid; e4 < n4; e4 += stride) {
        const int4 d = reinterpret_cast<const int4*>(dst)[e4];
        int4 r;
        r.x = atomicAdd(&g_deg[d.x], 1);
        r.y = atomicAdd(&g_deg[d.y], 1);
        r.z = atomicAdd(&g_deg[d.z], 1);
        r.w = atomicAdd(&g_deg[d.w], 1);
        reinterpret_cast<int4*>(g_rank)[e4] = r;
    }
    for (int e = (n4 << 2) + tid; e < n_edges; e += stride)
        g_rank[e] = atomicAdd(&g_deg[dst[e]], 1);
}

// ---------------------------------------------------------------------------
// scan phase 1: per-block exclusive scan of g_deg -> g_off, block sums
// ---------------------------------------------------------------------------
__global__ void __launch_bounds__(SCAN_BLK) scan1_kernel(int n) {
    __shared__ int warp_sums[32];
    const int t = threadIdx.x;
    const int i = blockIdx.x * SCAN_BLK + t;
    const int lane = t & 31;
    const int wid  = t >> 5;

    int v = (i < n) ? g_deg[i] : 0;

    int incl = v;
    #pragma unroll
    for (int d = 1; d < 32; d <<= 1) {
        int y = __shfl_up_sync(0xffffffffu, incl, d);
        if (lane >= d) incl += y;
    }
    if (lane == 31) warp_sums[wid] = incl;
    __syncthreads();

    if (wid == 0) {
        int s = warp_sums[lane];
        #pragma unroll
        for (int d = 1; d < 32; d <<= 1) {
            int y = __shfl_up_sync(0xffffffffu, s, d);
            if (lane >= d) s += y;
        }
        warp_sums[lane] = s;
    }
    __syncthreads();

    int woff = (wid > 0) ? warp_sums[wid - 1] : 0;
    int excl = woff + incl - v;

    if (i < n) g_off[i] = excl;
    if (t == SCAN_BLK - 1) g_bsum[blockIdx.x] = woff + incl;
}

// ---------------------------------------------------------------------------
// scan phase 3 with inline lookback: each block warp-reduces the block sums
// preceding its scan1-block, adds to its 256 offsets. (scan2 eliminated.)
// ---------------------------------------------------------------------------
__global__ void __launch_bounds__(256) scan3_kernel(int n, int n_edges) {
    __shared__ int s_pre;
    const int sb = blockIdx.x >> 2;   // owning scan1 block (1024/256)

    if (threadIdx.x < 32) {
        int sum = 0;
        for (int j = threadIdx.x; j < sb; j += 32) sum += g_bsum[j];
        #pragma unroll
        for (int d = 16; d; d >>= 1)
            sum += __shfl_xor_sync(0xffffffffu, sum, d);
        if (threadIdx.x == 0) s_pre = sum;
    }
    __syncthreads();

    const int i = blockIdx.x * 256 + threadIdx.x;
    if (i < n) g_off[i] += s_pre;
    if (i == 0) g_off[n] = n_edges;
}

// ---------------------------------------------------------------------------
// fill: atomic-free bucketing using precomputed ranks
// ---------------------------------------------------------------------------
__global__ void __launch_bounds__(256) fill_kernel(
    const int* __restrict__ src, const int* __restrict__ dst, int n_edges)
{
    const int tid    = blockIdx.x * blockDim.x + threadIdx.x;
    const int stride = gridDim.x * blockDim.x;
    const int n4     = n_edges >> 2;

    for (int e4 = tid; e4 < n4; e4 += stride) {
        const int4 s = reinterpret_cast<const int4*>(src)[e4];
        const int4 d = reinterpret_cast<const int4*>(dst)[e4];
        const int4 r = reinterpret_cast<const int4*>(g_rank)[e4];
        g_edge_src[__ldg(&g_off[d.x]) + r.x] = s.x;
        g_edge_src[__ldg(&g_off[d.y]) + r.y] = s.y;
        g_edge_src[__ldg(&g_off[d.z]) + r.z] = s.z;
        g_edge_src[__ldg(&g_off[d.w]) + r.w] = s.w;
    }
    for (int e = (n4 << 2) + tid; e < n_edges; e += stride)
        g_edge_src[__ldg(&g_off[dst[e]]) + g_rank[e]] = src[e];
}

// ---------------------------------------------------------------------------
// GEMM half: Y[:, c0:c0+64] = feat @ W[c0:c0+64, :]^T
// Packed fma.rn.f32x2. Block: 256 thr; tile 128 rows x 64 cols;
// thread (tx=tid&15, ty=tid>>4): 8 rows x 4 cols.
// ---------------------------------------------------------------------------
#define WT2 68   // 64 cols + 4 pad (floats)

__device__ __forceinline__ unsigned long long pk2(float f) {
    unsigned long long r;
    asm("mov.b64 %0, {%1, %1};" : "=l"(r) : "f"(f));
    return r;
}
#define FMA2(d, a, b) \
    asm("fma.rn.f32x2 %0, %1, %2, %0;" : "+l"(d) : "l"(a), "l"(b))

__global__ void __launch_bounds__(256) gemm_half_kernel(
    const float* __restrict__ feat,   // [M, 128]
    const float* __restrict__ W,      // [128, 128] row-major: W[c][k]
    int M, int c0)
{
    __shared__ float Wt[128 * WT2];   // Wt[k][c] = W[c0+c][k], 34.8 KB

    const int tid = threadIdx.x;
    const int tx  = tid & 15;    // column group (4 cols of this half)
    const int ty  = tid >> 4;    // row group (8 rows)

    #pragma unroll
    for (int i = tid; i < 64 * 128; i += 256) {
        int c = i >> 7;      // 0..63
        int k = i & 127;
        Wt[k * WT2 + c] = W[(c0 + c) * N_FEATS + k];
    }
    __syncthreads();

    const int row0 = blockIdx.x * 128 + ty * 8;

    const float* ap[8];
    #pragma unroll
    for (int r = 0; r < 8; r++) {
        int rr = row0 + r;
        if (rr > M - 1) rr = M - 1;
        ap[r] = feat + (size_t)rr * N_FEATS;
    }

    unsigned long long acc[8][2];
    #pragma unroll
    for (int r = 0; r < 8; r++) { acc[r][0] = 0ull; acc[r][1] = 0ull; }

    #pragma unroll 2
    for (int k0 = 0; k0 < 128; k0 += 4) {
        ulonglong2 wv[4];
        #pragma unroll
        for (int kk = 0; kk < 4; kk++)
            wv[kk] = *reinterpret_cast<const ulonglong2*>(
                &Wt[(k0 + kk) * WT2 + tx * 4]);

        #pragma unroll
        for (int r = 0; r < 8; r++) {
            const float4 a4 = *reinterpret_cast<const float4*>(ap[r] + k0);
            const unsigned long long f0 = pk2(a4.x);
            const unsigned long long f1 = pk2(a4.y);
            const unsigned long long f2 = pk2(a4.z);
            const unsigned long long f3 = pk2(a4.w);
            FMA2(acc[r][0], f0, wv[0].x);  FMA2(acc[r][1], f0, wv[0].y);
            FMA2(acc[r][0], f1, wv[1].x);  FMA2(acc[r][1], f1, wv[1].y);
            FMA2(acc[r][0], f2, wv[2].x);  FMA2(acc[r][1], f2, wv[2].y);
            FMA2(acc[r][0], f3, wv[3].x);  FMA2(acc[r][1], f3, wv[3].y);
        }
    }

    #pragma unroll
    for (int r = 0; r < 8; r++) {
        const int row = row0 + r;
        if (row < M) {
            float a0, a1, a2, a3;
            asm("mov.b64 {%0, %1}, %2;" : "=f"(a0), "=f"(a1) : "l"(acc[r][0]));
            asm("mov.b64 {%0, %1}, %2;" : "=f"(a2), "=f"(a3) : "l"(acc[r][1]));
            *reinterpret_cast<float4*>(
                g_y + (size_t)row * N_FEATS + c0 + tx * 4) =
                make_float4(a0, a1, a2, a3);
        }
    }
}

// ---------------------------------------------------------------------------
// gather half: aggregate Y[:, c0:c0+64] per node + bias + ReLU -> out half.
// Warp per node; lane owns 2 contiguous feats (float2, 256B/warp coalesced).
// ---------------------------------------------------------------------------
__global__ void __launch_bounds__(256) gather_half_kernel(
    const float* __restrict__ bias,
    float* __restrict__ out,
    int n_nodes, int c0)
{
    const int lane    = threadIdx.x & 31;
    const int warp    = (blockIdx.x * blockDim.x + threadIdx.x) >> 5;
    const int n_warps = (gridDim.x * blockDim.x) >> 5;

    const float2 bv = *reinterpret_cast<const float2*>(bias + c0 + lane * 2);

    for (int n = warp; n < n_nodes; n += n_warps) {
        const int beg = g_off[n];
        const int end = g_off[n + 1];

        float2 acc = make_float2(0.f, 0.f);

        for (int i = beg; i < end; i += 32) {
            const int cnt = min(32, end - i);
            int s = (lane < cnt) ? g_edge_src[i + lane] : 0;
            #pragma unroll 8
            for (int j = 0; j < cnt; j++) {
                const int sj = __shfl_sync(0xffffffffu, s, j);
                const float2 v = *reinterpret_cast<const float2*>(
                    g_y + (size_t)sj * N_FEATS + c0 + lane * 2);
                acc.x += v.x; acc.y += v.y;
            }
        }

        float2 o;
        o.x = fmaxf(acc.x + bv.x, 0.f);
        o.y = fmaxf(acc.y + bv.y, 0.f);
        *reinterpret_cast<float2*>(
            out + (size_t)n * N_FEATS + c0 + lane * 2) = o;
    }
}

// ---------------------------------------------------------------------------
extern "C" void kernel_launch(void* const* d_in, const int* in_sizes, int n_in,
                              void* d_out, int out_size)
{
    const float* feat = (const float*)d_in[0];
    const int*   src  = (const int*)d_in[1];
    const int*   dst  = (const int*)d_in[2];
    const float* W    = (const float*)d_in[3];
    const float* bias = (const float*)d_in[4];
    float*       out  = (float*)d_out;

    const int n_edges = in_sizes[1];
    const int M       = in_sizes[0] / N_FEATS;   // 100000 nodes
    const int nblk    = (M + SCAN_BLK - 1) / SCAN_BLK;

    cudaStream_t s2;
    cudaStreamCreateWithFlags(&s2, cudaStreamNonBlocking);
    cudaEvent_t ev_fork, ev_gA, ev_gB;
    cudaEventCreateWithFlags(&ev_fork, cudaEventDisableTiming);
    cudaEventCreateWithFlags(&ev_gA,   cudaEventDisableTiming);
    cudaEventCreateWithFlags(&ev_gB,   cudaEventDisableTiming);

    // fork GEMM branch first (it has no dependency on the memset)
    cudaEventRecord(ev_fork, 0);
    cudaStreamWaitEvent(s2, ev_fork, 0);
    const int ggrid = (M + 127) / 128;
    gemm_half_kernel<<<ggrid, 256, 0, s2>>>(feat, W, M, 0);
    cudaEventRecord(ev_gA, s2);
    gemm_half_kernel<<<ggrid, 256, 0, s2>>>(feat, W, M, 64);
    cudaEventRecord(ev_gB, s2);

    // main stream: CSR build
    void* deg_ptr = nullptr;
    cudaGetSymbolAddress(&deg_ptr, g_deg);
    cudaMemsetAsync(deg_ptr, 0, (size_t)M * sizeof(int), 0);
    hist_rank_kernel<<<1184, 256>>>(dst, n_edges);
    scan1_kernel<<<nblk, SCAN_BLK>>>(M);
    scan3_kernel<<<(M + 255) / 256, 256>>>(M, n_edges);
    fill_kernel<<<1184, 256>>>(src, dst, n_edges);

    // pipelined gathers
    cudaStreamWaitEvent(0, ev_gA, 0);
    gather_half_kernel<<<1184, 256>>>(bias, out, M, 0);
    cudaStreamWaitEvent(0, ev_gB, 0);
    gather_half_kernel<<<1184, 256>>>(bias, out, M, 64);

    cudaEventDestroy(ev_fork);
    cudaEventDestroy(ev_gA);
    cudaEventDestroy(ev_gB);
    cudaStreamDestroy(s2);
}

// round 7
// speedup vs baseline: 1.8962x; 1.3885x over previous
#include <cuda_runtime.h>
#include <cuda_bf16.h>
#include <cstdint>

// GCN layer: out = ReLU( segment_sum(feature[src], dst) @ W^T + b )
// N=100000, E=1.6M, 128 feats, fp32. src/dst int32.
//
// R7: GEMM on tensor cores via base-ISA mma.sync m16n8k16 bf16 (tcgen05 is
// gated behind sm_103a PTX, which this harness's compute_103 target lacks).
// Exact bf16 hi/lo split, 3 MMA combos, fp32 accum -> ~1e-5 rel err.
//   s2 :  gemm_mma (Y = feat @ W^T)
//   main: memset -> hist(+rank) -> scan1 -> scan3 -> fill -> join -> gather

#define N_FEATS   128
#define MAX_NODES 100000
#define MAX_EDGES 1600000
#define SCAN_BLK  1024
#define N_SCAN_BLKS ((MAX_NODES + SCAN_BLK - 1) / SCAN_BLK)   // 98

__device__ float g_y[MAX_NODES * N_FEATS];     // Y = feat @ W^T
__device__ int   g_deg[MAX_NODES];
__device__ int   g_off[MAX_NODES + 1];
__device__ int   g_bsum[N_SCAN_BLKS];
__device__ int   g_rank[MAX_EDGES];
__device__ int   g_edge_src[MAX_EDGES];

// ---------------------------------------------------------------------------
// exact split: x = hi(bf16 trunc) + lo(bf16 rn); packs a pair into bf16x2.
// low 16 bits = first element, high 16 = second (matches fragment layout).
// ---------------------------------------------------------------------------
__device__ __forceinline__ void split2(float a, float b,
                                       uint32_t& hi, uint32_t& lo)
{
    uint32_t ba = __float_as_uint(a), bb = __float_as_uint(b);
    uint32_t ha = ba & 0xffff0000u,   hb = bb & 0xffff0000u;
    hi = (ha >> 16) | hb;
    float la = a - __uint_as_float(ha);
    float lb = b - __uint_as_float(hb);
    asm("cvt.rn.bf16x2.f32 %0, %2, %1;" : "=r"(lo) : "f"(la), "f"(lb));
}

#define MMA16816(d, a, b)                                                     \
    asm volatile(                                                             \
        "mma.sync.aligned.m16n8k16.row.col.f32.bf16.bf16.f32 "               \
        "{%0,%1,%2,%3}, {%4,%5,%6,%7}, {%8,%9}, {%0,%1,%2,%3};"              \
        : "+f"((d)[0]), "+f"((d)[1]), "+f"((d)[2]), "+f"((d)[3])              \
        : "r"((a)[0]), "r"((a)[1]), "r"((a)[2]), "r"((a)[3]),                 \
          "r"((b)[0]), "r"((b)[1]))

// ---------------------------------------------------------------------------
// GEMM: Y = feat @ W^T.  Block 256 thr = 8 warps; tile 128 rows x 128 cols.
// Warp w: rows (w>>1)*32 .. +31 (2 m-tiles), cols (w&1)*64 .. +63 (8 n-tiles).
// Fragments loaded straight from global (32-bit pairs, sector-coalesced).
// ---------------------------------------------------------------------------
__global__ void __launch_bounds__(256) gemm_mma_kernel(
    const float* __restrict__ feat,   // [M, 128]
    const float* __restrict__ W,      // [128, 128] row-major: W[n][k]
    int M)
{
    const int tid  = threadIdx.x;
    const int wid  = tid >> 5;
    const int lane = tid & 31;
    const int g    = lane >> 2;       // group id (row within tile quadrant)
    const int t    = lane & 3;        // thread in group (k/col pairs)

    const int rbase = blockIdx.x * 128 + (wid >> 1) * 32;
    const int cbase = (wid & 1) * 64;

    // clamped row pointers for the 4 distinct A rows this thread touches
    const float* arow[2][2];
    #pragma unroll
    for (int mt = 0; mt < 2; mt++) {
        int rlo = rbase + mt * 16 + g;
        int rhi = rlo + 8;
        if (rlo > M - 1) rlo = M - 1;
        if (rhi > M - 1) rhi = M - 1;
        arow[mt][0] = feat + (size_t)rlo * N_FEATS;
        arow[mt][1] = feat + (size_t)rhi * N_FEATS;
    }

    float acc[2][8][4];
    #pragma unroll
    for (int mt = 0; mt < 2; mt++)
        #pragma unroll
        for (int nt = 0; nt < 8; nt++)
            #pragma unroll
            for (int q = 0; q < 4; q++)
                acc[mt][nt][q] = 0.f;

    #pragma unroll 2
    for (int ks = 0; ks < 8; ks++) {
        const int k0 = ks * 16;

        // A fragments (hi/lo), order {a0,a1,a2,a3} =
        // (row g, k-lo), (row g+8, k-lo), (row g, k-hi), (row g+8, k-hi)
        uint32_t Ah[2][4], Al[2][4];
        #pragma unroll
        for (int mt = 0; mt < 2; mt++) {
            const float2 a0 = *reinterpret_cast<const float2*>(
                arow[mt][0] + k0 + 2 * t);
            const float2 a1 = *reinterpret_cast<const float2*>(
                arow[mt][1] + k0 + 2 * t);
            const float2 a2 = *reinterpret_cast<const float2*>(
                arow[mt][0] + k0 + 2 * t + 8);
            const float2 a3 = *reinterpret_cast<const float2*>(
                arow[mt][1] + k0 + 2 * t + 8);
            split2(a0.x, a0.y, Ah[mt][0], Al[mt][0]);
            split2(a1.x, a1.y, Ah[mt][1], Al[mt][1]);
            split2(a2.x, a2.y, Ah[mt][2], Al[mt][2]);
            split2(a3.x, a3.y, Ah[mt][3], Al[mt][3]);
        }

        #pragma unroll
        for (int nt = 0; nt < 8; nt++) {
            const int n = cbase + nt * 8 + g;
            const float2 b0 = *reinterpret_cast<const float2*>(
                W + (size_t)n * N_FEATS + k0 + 2 * t);
            const float2 b1 = *reinterpret_cast<const float2*>(
                W + (size_t)n * N_FEATS + k0 + 2 * t + 8);
            uint32_t Bh[2], Bl[2];
            split2(b0.x, b0.y, Bh[0], Bl[0]);
            split2(b1.x, b1.y, Bh[1], Bl[1]);

            #pragma unroll
            for (int mt = 0; mt < 2; mt++) {
                MMA16816(acc[mt][nt], Ah[mt], Bh);
                MMA16816(acc[mt][nt], Ah[mt], Bl);
                MMA16816(acc[mt][nt], Al[mt], Bh);
            }
        }
    }

    // store: c0,c1 = D[g][2t..2t+1]; c2,c3 = D[g+8][2t..2t+1]
    #pragma unroll
    for (int mt = 0; mt < 2; mt++) {
        const int rlo = rbase + mt * 16 + g;
        const int rhi = rlo + 8;
        #pragma unroll
        for (int nt = 0; nt < 8; nt++) {
            const int col = cbase + nt * 8 + 2 * t;
            if (rlo < M)
                *reinterpret_cast<float2*>(g_y + (size_t)rlo * N_FEATS + col) =
                    make_float2(acc[mt][nt][0], acc[mt][nt][1]);
            if (rhi < M)
                *reinterpret_cast<float2*>(g_y + (size_t)rhi * N_FEATS + col) =
                    make_float2(acc[mt][nt][2], acc[mt][nt][3]);
        }
    }
}

// ======================= CSR build =========================================
__global__ void __launch_bounds__(256) hist_rank_kernel(
    const int* __restrict__ dst, int n_edges)
{
    const int tid    = blockIdx.x * blockDim.x + threadIdx.x;
    const int stride = gridDim.x * blockDim.x;
    const int n4     = n_edges >> 2;

    for (int e4 = tid; e4 < n4; e4 += stride) {
        const int4 d = reinterpret_cast<const int4*>(dst)[e4];
        int4 r;
        r.x = atomicAdd(&g_deg[d.x], 1);
        r.y = atomicAdd(&g_deg[d.y], 1);
        r.z = atomicAdd(&g_deg[d.z], 1);
        r.w = atomicAdd(&g_deg[d.w], 1);
        reinterpret_cast<int4*>(g_rank)[e4] = r;
    }
    for (int e = (n4 << 2) + tid; e < n_edges; e += stride)
        g_rank[e] = atomicAdd(&g_deg[dst[e]], 1);
}

__global__ void __launch_bounds__(SCAN_BLK) scan1_kernel(int n) {
    __shared__ int warp_sums[32];
    const int t = threadIdx.x;
    const int i = blockIdx.x * SCAN_BLK + t;
    const int lane = t & 31;
    const int wid  = t >> 5;

    int v = (i < n) ? g_deg[i] : 0;

    int incl = v;
    #pragma unroll
    for (int d = 1; d < 32; d <<= 1) {
        int y = __shfl_up_sync(0xffffffffu, incl, d);
        if (lane >= d) incl += y;
    }
    if (lane == 31) warp_sums[wid] = incl;
    __syncthreads();

    if (wid == 0) {
        int s = warp_sums[lane];
        #pragma unroll
        for (int d = 1; d < 32; d <<= 1) {
            int y = __shfl_up_sync(0xffffffffu, s, d);
            if (lane >= d) s += y;
        }
        warp_sums[lane] = s;
    }
    __syncthreads();

    int woff = (wid > 0) ? warp_sums[wid - 1] : 0;
    int excl = woff + incl - v;

    if (i < n) g_off[i] = excl;
    if (t == SCAN_BLK - 1) g_bsum[blockIdx.x] = woff + incl;
}

__global__ void __launch_bounds__(256) scan3_kernel(int n, int n_edges) {
    __shared__ int s_pre;
    const int sb = blockIdx.x >> 2;

    if (threadIdx.x < 32) {
        int sum = 0;
        for (int j = threadIdx.x; j < sb; j += 32) sum += g_bsum[j];
        #pragma unroll
        for (int d = 16; d; d >>= 1)
            sum += __shfl_xor_sync(0xffffffffu, sum, d);
        if (threadIdx.x == 0) s_pre = sum;
    }
    __syncthreads();

    const int i = blockIdx.x * 256 + threadIdx.x;
    if (i < n) g_off[i] += s_pre;
    if (i == 0) g_off[n] = n_edges;
}

__global__ void __launch_bounds__(256) fill_kernel(
    const int* __restrict__ src, const int* __restrict__ dst, int n_edges)
{
    const int tid    = blockIdx.x * blockDim.x + threadIdx.x;
    const int stride = gridDim.x * blockDim.x;
    const int n4     = n_edges >> 2;

    for (int e4 = tid; e4 < n4; e4 += stride) {
        const int4 s = reinterpret_cast<const int4*>(src)[e4];
        const int4 d = reinterpret_cast<const int4*>(dst)[e4];
        const int4 r = reinterpret_cast<const int4*>(g_rank)[e4];
        g_edge_src[__ldg(&g_off[d.x]) + r.x] = s.x;
        g_edge_src[__ldg(&g_off[d.y]) + r.y] = s.y;
        g_edge_src[__ldg(&g_off[d.z]) + r.z] = s.z;
        g_edge_src[__ldg(&g_off[d.w]) + r.w] = s.w;
    }
    for (int e = (n4 << 2) + tid; e < n_edges; e += stride)
        g_edge_src[__ldg(&g_off[dst[e]]) + g_rank[e]] = src[e];
}

// ---------------------------------------------------------------------------
// gather: full-width aggregate of Y + bias + ReLU -> out.
// Warp per node; lane owns 4 contiguous feats (float4, 512B/warp coalesced).
// ---------------------------------------------------------------------------
__global__ void __launch_bounds__(256) gather_epi_kernel(
    const float* __restrict__ bias,
    float* __restrict__ out,
    int n_nodes)
{
    const int lane    = threadIdx.x & 31;
    const int warp    = (blockIdx.x * blockDim.x + threadIdx.x) >> 5;
    const int n_warps = (gridDim.x * blockDim.x) >> 5;

    const float4 bv = *reinterpret_cast<const float4*>(bias + lane * 4);

    for (int n = warp; n < n_nodes; n += n_warps) {
        const int beg = g_off[n];
        const int end = g_off[n + 1];

        float4 acc = make_float4(0.f, 0.f, 0.f, 0.f);

        for (int i = beg; i < end; i += 32) {
            const int cnt = min(32, end - i);
            int s = (lane < cnt) ? g_edge_src[i + lane] : 0;
            #pragma unroll 4
            for (int j = 0; j < cnt; j++) {
                const int sj = __shfl_sync(0xffffffffu, s, j);
                const float4 v = *reinterpret_cast<const float4*>(
                    g_y + (size_t)sj * N_FEATS + lane * 4);
                acc.x += v.x; acc.y += v.y; acc.z += v.z; acc.w += v.w;
            }
        }

        float4 o;
        o.x = fmaxf(acc.x + bv.x, 0.f);
        o.y = fmaxf(acc.y + bv.y, 0.f);
        o.z = fmaxf(acc.z + bv.z, 0.f);
        o.w = fmaxf(acc.w + bv.w, 0.f);
        *reinterpret_cast<float4*>(out + (size_t)n * N_FEATS + lane * 4) = o;
    }
}

// ---------------------------------------------------------------------------
extern "C" void kernel_launch(void* const* d_in, const int* in_sizes, int n_in,
                              void* d_out, int out_size)
{
    const float* feat = (const float*)d_in[0];
    const int*   src  = (const int*)d_in[1];
    const int*   dst  = (const int*)d_in[2];
    const float* W    = (const float*)d_in[3];
    const float* bias = (const float*)d_in[4];
    float*       out  = (float*)d_out;

    const int n_edges = in_sizes[1];
    const int M       = in_sizes[0] / N_FEATS;   // 100000 nodes
    const int nblk    = (M + SCAN_BLK - 1) / SCAN_BLK;

    cudaStream_t s2;
    cudaStreamCreateWithFlags(&s2, cudaStreamNonBlocking);
    cudaEvent_t ev_fork, ev_join;
    cudaEventCreateWithFlags(&ev_fork, cudaEventDisableTiming);
    cudaEventCreateWithFlags(&ev_join, cudaEventDisableTiming);

    // fork tensor-core GEMM
    cudaEventRecord(ev_fork, 0);
    cudaStreamWaitEvent(s2, ev_fork, 0);
    gemm_mma_kernel<<<(M + 127) / 128, 256, 0, s2>>>(feat, W, M);
    cudaEventRecord(ev_join, s2);

    // main stream: CSR build
    void* deg_ptr = nullptr;
    cudaGetSymbolAddress(&deg_ptr, g_deg);
    cudaMemsetAsync(deg_ptr, 0, (size_t)M * sizeof(int), 0);
    hist_rank_kernel<<<1184, 256>>>(dst, n_edges);
    scan1_kernel<<<nblk, SCAN_BLK>>>(M);
    scan3_kernel<<<(M + 255) / 256, 256>>>(M, n_edges);
    fill_kernel<<<1184, 256>>>(src, dst, n_edges);

    // join, then gather + bias + ReLU
    cudaStreamWaitEvent(0, ev_join, 0);
    gather_epi_kernel<<<1184, 256>>>(bias, out, M);

    cudaEventDestroy(ev_fork);
    cudaEventDestroy(ev_join);
    cudaStreamDestroy(s2);
}